// round 2
// baseline (speedup 1.0000x reference)
#include <cuda_runtime.h>

// Problem constants
#define B_N   16
#define LATD  512
#define FIN   128
#define FOUT  128
#define HH    64
#define WWC   64
#define KSZ   147456        // FOUT*FIN*3*3
#define JTOT  147584        // KSZ + FOUT

// Conv tiling
#define CO_T  64
#define TH    8
#define TW    32
#define CI_T  8

// Scratch for the generated per-sample kernels + biases (9.4 MB)
__device__ float g_ks[(size_t)B_N * JTOT];

typedef unsigned long long ull;

__device__ __forceinline__ ull pack2(float lo, float hi) {
    ull r;
    asm("mov.b64 %0, {%1, %2};" : "=l"(r) : "f"(lo), "f"(hi));
    return r;
}
__device__ __forceinline__ void unpack2(ull v, float &lo, float &hi) {
    asm("mov.b64 {%0, %1}, %2;" : "=f"(lo), "=f"(hi) : "l"(v));
}
// packed dual-lane fp32 FMA (sm_103a): d = a*b + d, lanewise on 2xf32
__device__ __forceinline__ void ffma2(ull &d, ull a, ull b) {
    asm("fma.rn.f32x2 %0, %1, %2, %0;" : "+l"(d) : "l"(a), "l"(b));
}

// ---------------------------------------------------------------------------
// Kernel 1: ks[b][j] = sum_l lat[b][l] * W[j][l] + bias[j]
// One thread per j; lat (16x512) staged in smem, broadcast reads.
// W rows streamed via float4 (full 128B line consumption via L1 temporal reuse).
// ---------------------------------------------------------------------------
__global__ void __launch_bounds__(256) ks_gemm_kernel(const float* __restrict__ lat,
                                                      const float* __restrict__ W,
                                                      const float* __restrict__ bias) {
    __shared__ float4 lat_s[B_N * (LATD / 4)];   // 2048 float4 = 32 KB
    const int tid = threadIdx.x;
    const float4* lat4 = reinterpret_cast<const float4*>(lat);
    for (int i = tid; i < B_N * (LATD / 4); i += 256) lat_s[i] = lat4[i];
    __syncthreads();

    const int j = blockIdx.x * 256 + tid;
    if (j >= JTOT) return;

    float acc[B_N];
#pragma unroll
    for (int b = 0; b < B_N; b++) acc[b] = 0.f;

    const float4* Wr = reinterpret_cast<const float4*>(W + (size_t)j * LATD);
#pragma unroll 2
    for (int kk = 0; kk < LATD / 4; kk++) {
        const float4 w = Wr[kk];
#pragma unroll
        for (int b = 0; b < B_N; b++) {
            const float4 l = lat_s[b * (LATD / 4) + kk];
            acc[b] += w.x * l.x + w.y * l.y + w.z * l.z + w.w * l.w;
        }
    }
    const float bj = bias[j];
#pragma unroll
    for (int b = 0; b < B_N; b++)
        g_ks[(size_t)b * JTOT + j] = acc[b] + bj;
}

// ---------------------------------------------------------------------------
// Kernel 2: per-sample 3x3 conv with the generated kernels.
// Grid: x = 16 spatial tiles (8 row-tiles x 2 col-tiles), y = co tile (2), z = b (16).
// Block: 256 threads. Thread = 8 output channels (4 packed co-pairs) x 8 rows x 1 col.
// Inner loop on packed fma.rn.f32x2 over co-pairs; kern smem is pair-interleaved
// so each co-pair load is a single LDS.64 broadcast.
// ---------------------------------------------------------------------------
__global__ void __launch_bounds__(256, 2) dynconv_kernel(const float* __restrict__ x,
                                                         float* __restrict__ y) {
    __shared__ float x_s[CI_T * 10 * 36];            // 2880 floats (pitch 36)
    __shared__ float k_s[(CO_T / 2) * 72 * 2];       // 4608 floats, pair-interleaved

    const int tid     = threadIdx.x;
    const int b       = blockIdx.z;
    const int co_base = blockIdx.y * CO_T;
    const int sp      = blockIdx.x;                  // 0..15
    const int r0      = (sp >> 1) * TH;
    const int c0      = (sp & 1) * TW;
    const int tcol    = tid & 31;
    const int cg      = tid >> 5;                    // warp id = co-group (0..7)

    const float* kb = g_ks + (size_t)b * JTOT;

    ull acc[4][8];
#pragma unroll
    for (int p = 0; p < 4; p++)
#pragma unroll
        for (int r = 0; r < 8; r++) acc[p][r] = 0ULL;

    for (int cic = 0; cic < FIN / CI_T; cic++) {
        // ---- stage x tile (CI_T channels, 10 rows x 34 cols with halo, zero-padded)
        const float* xb = x + ((size_t)b * FIN + cic * CI_T) * (HH * WWC);
        for (int idx = tid; idx < CI_T * 10 * 34; idx += 256) {
            const int ci  = idx / 340;
            const int rem = idx - ci * 340;
            const int r   = rem / 34;
            const int c   = rem - r * 34;
            const int gr  = r0 + r - 1;
            const int gc  = c0 + c - 1;
            float v = 0.f;
            if (gr >= 0 && gr < HH && gc >= 0 && gc < WWC)
                v = xb[ci * (HH * WWC) + gr * WWC + gc];
            x_s[ci * 360 + r * 36 + c] = v;
        }
        // ---- stage kern tile (64 co x 8 ci x 9 taps), pair-interleaved over co
        for (int idx = tid; idx < CO_T * 72; idx += 256) {
            const int co_l = idx / 72;
            const int rr   = idx - co_l * 72;        // ci_l*9 + kk
            const float v  = kb[(size_t)(co_base + co_l) * 1152 + cic * 72 + rr];
            k_s[((co_l >> 1) * 72 + rr) * 2 + (co_l & 1)] = v;
        }
        __syncthreads();

        // ---- compute
#pragma unroll 1
        for (int ci = 0; ci < CI_T; ci++) {
            const float* xr = &x_s[ci * 360];
            const float* kr = &k_s[(cg * 4) * 72 * 2 + ci * 9 * 2];
#pragma unroll
            for (int kw = 0; kw < 3; kw++) {
                ull xd[10];
#pragma unroll
                for (int r = 0; r < 10; r++) {
                    const float v = xr[r * 36 + tcol + kw];
                    xd[r] = pack2(v, v);
                }
#pragma unroll
                for (int kh = 0; kh < 3; kh++) {
#pragma unroll
                    for (int pi = 0; pi < 4; pi++) {
                        const int pidx = pi * 72 * 2 + (kh * 3 + kw) * 2;
                        const ull kv = pack2(kr[pidx], kr[pidx + 1]);
#pragma unroll
                        for (int r = 0; r < 8; r++)
                            ffma2(acc[pi][r], kv, xd[r + kh]);
                    }
                }
            }
        }
        __syncthreads();
    }

    // ---- epilogue: unpack, add generated bias, store
#pragma unroll
    for (int pi = 0; pi < 4; pi++) {
        const int co0 = co_base + cg * 8 + 2 * pi;
        const float b0 = kb[KSZ + co0];
        const float b1 = kb[KSZ + co0 + 1];
#pragma unroll
        for (int r = 0; r < 8; r++) {
            float lo, hi;
            unpack2(acc[pi][r], lo, hi);
            const int gr = r0 + r;
            const int gc = c0 + tcol;
            y[(((size_t)b * FOUT + co0) * HH + gr) * WWC + gc]       = lo + b0;
            y[(((size_t)b * FOUT + co0 + 1) * HH + gr) * WWC + gc]   = hi + b1;
        }
    }
}

// ---------------------------------------------------------------------------
// Inputs (metadata order): x (16,128,64,64) f32 | lat (16,512) f32
//                          W (147584,512) f32   | b (147584,) f32
// Output: (16,128,64,64) f32
// ---------------------------------------------------------------------------
extern "C" void kernel_launch(void* const* d_in, const int* in_sizes, int n_in,
                              void* d_out, int out_size) {
    const float* x    = (const float*)d_in[0];
    const float* lat  = (const float*)d_in[1];
    const float* W    = (const float*)d_in[2];
    const float* bias = (const float*)d_in[3];
    float* y = (float*)d_out;

    const int gemm_blocks = (JTOT + 255) / 256;
    ks_gemm_kernel<<<gemm_blocks, 256>>>(lat, W, bias);

    dim3 grid(16, FOUT / CO_T, B_N);
    dynconv_kernel<<<grid, 256>>>(x, y);
}